// round 3
// baseline (speedup 1.0000x reference)
#include <cuda_runtime.h>
#include <math.h>

#define NJ 17
#define ND 128
#define NH 2
#define NDH 64
#define NITER 4
#define LNEPS 1e-5f
#define NTHREADS 256
#define XSTR 20          // padded row stride for transposed xn tile

// ---- fixed 17-node skeleton adjacency (incl. self), flattened neighbor lists ----
__constant__ int c_nbr_off[18] = {0,4,7,10,12,15,18,20,23,28,31,33,36,39,41,44,47,49};
__constant__ int c_nbr[49] = {
    0,1,4,7,  0,1,2,  1,2,3,  2,3,  0,4,5,  4,5,6,  5,6,  0,7,8,
    7,8,9,11,14,  8,9,10,  9,10,  8,11,12,  11,12,13,  12,13,
    8,14,15,  14,15,16,  15,16};
__constant__ int c_edge_i[49] = {
    0,0,0,0,  1,1,1,  2,2,2,  3,3,  4,4,4,  5,5,5,  6,6,  7,7,7,
    8,8,8,8,8,  9,9,9,  10,10,  11,11,11,  12,12,12,  13,13,
    14,14,14,  15,15,15,  16,16};

// NOTE: every member that is accessed via float4 (LDS.128/STS.128) must be
// 16-byte aligned. The R1 crash was psW landing at offset ≡ 12 (mod 16)
// because scs(392B)+skipv(68B) preceded it. alignas(16) everywhere fixes it.
struct SmemLayout {
    alignas(16) float xs[NJ][ND];        // current x tile
    alignas(16) float x0s[NJ][ND];       // post-outer-LN fixed point
    alignas(16) float xnT[ND][XSTR];     // xn transposed (k-major); 80B row stride (16-mult)
    alignas(16) float Ls[NJ][2*ND];
    alignas(16) float Rs[NJ][2*ND];
    alignas(16) float Vs[NJ][ND];
    alignas(16) float scs[2*49];         // attention scores by (head, edge)
    alignas(16) float skipv[NJ];
    alignas(16) float lnG[ND];
    alignas(16) float lnB[ND];
    alignas(16) float aW[ND];
    alignas(16) float psW[ND];
    alignas(16) float vbs[ND];
    alignas(16) float b1s[2*ND];
    alignas(16) float b2s[2*ND];
    alignas(16) float alpha_b0;
    float ps_b0;
};

__device__ __forceinline__ float wredsum(float v) {
    #pragma unroll
    for (int o = 16; o; o >>= 1) v += __shfl_xor_sync(0xffffffffu, v, o);
    return v;
}

__global__ void __launch_bounds__(NTHREADS, 2)
spatial_appnp_kernel(
    const float* __restrict__ x,
    const float* __restrict__ og,  const float* __restrict__ ob,
    const float* __restrict__ lg,  const float* __restrict__ lb,
    const float* __restrict__ aw,  const float* __restrict__ ab,
    const float* __restrict__ w1,  const float* __restrict__ b1,
    const float* __restrict__ w2,  const float* __restrict__ b2,
    const float* __restrict__ psw, const float* __restrict__ psb,
    const float* __restrict__ vw,  const float* __restrict__ vb,
    float* __restrict__ out)
{
    extern __shared__ float smem_raw[];
    SmemLayout* sm = reinterpret_cast<SmemLayout*>(smem_raw);

    const int tid  = threadIdx.x;
    const int lane = tid & 31;
    const int wid  = tid >> 5;
    const int tile = blockIdx.x;
    const float* xg = x + (size_t)tile * NJ * ND;

    // cache small parameter vectors in SMEM
    for (int i = tid; i < ND; i += NTHREADS) {
        sm->lnG[i] = lg[i]; sm->lnB[i] = lb[i];
        sm->aW[i]  = aw[i]; sm->psW[i] = psw[i];
        sm->vbs[i] = vb[i];
    }
    for (int i = tid; i < 2*ND; i += NTHREADS) { sm->b1s[i] = b1[i]; sm->b2s[i] = b2[i]; }
    if (tid == 0) { sm->alpha_b0 = ab[0]; sm->ps_b0 = psb[0]; }

    // ---- outer LayerNorm: x -> xs, x0s ----
    for (int j = wid; j < NJ; j += 8) {
        const float4 v = reinterpret_cast<const float4*>(xg + j*ND)[lane];
        const float mean = wredsum(v.x+v.y+v.z+v.w) * (1.0f/ND);
        const float d0=v.x-mean, d1=v.y-mean, d2=v.z-mean, d3=v.w-mean;
        const float var = wredsum(d0*d0+d1*d1+d2*d2+d3*d3) * (1.0f/ND);
        const float rs = rsqrtf(var + LNEPS);
        const int c = lane*4;
        float4 r;
        r.x = d0*rs*og[c+0] + ob[c+0];
        r.y = d1*rs*og[c+1] + ob[c+1];
        r.z = d2*rs*og[c+2] + ob[c+2];
        r.w = d3*rs*og[c+3] + ob[c+3];
        reinterpret_cast<float4*>(sm->xs[j])[lane]  = r;
        reinterpret_cast<float4*>(sm->x0s[j])[lane] = r;
    }
    __syncthreads();

    for (int it = 0; it < NITER; ++it) {
        // ---- Phase 1: inner LN(xs) -> xnT (transposed), skip gate ----
        for (int j = wid; j < NJ; j += 8) {
            const float4 v = reinterpret_cast<const float4*>(sm->xs[j])[lane];
            const float mean = wredsum(v.x+v.y+v.z+v.w) * (1.0f/ND);
            const float d0=v.x-mean, d1=v.y-mean, d2=v.z-mean, d3=v.w-mean;
            const float var = wredsum(d0*d0+d1*d1+d2*d2+d3*d3) * (1.0f/ND);
            const float rs = rsqrtf(var + LNEPS);
            const int c = lane*4;
            const float y0 = d0*rs*sm->lnG[c+0] + sm->lnB[c+0];
            const float y1 = d1*rs*sm->lnG[c+1] + sm->lnB[c+1];
            const float y2 = d2*rs*sm->lnG[c+2] + sm->lnB[c+2];
            const float y3 = d3*rs*sm->lnG[c+3] + sm->lnB[c+3];
            float dot = y0*sm->aW[c+0] + y1*sm->aW[c+1] + y2*sm->aW[c+2] + y3*sm->aW[c+3];
            dot = wredsum(dot);
            if (lane == 0)
                sm->skipv[j] = 1.0f / (1.0f + expf(-(dot + sm->alpha_b0)));
            sm->xnT[c+0][j] = y0; sm->xnT[c+1][j] = y1;
            sm->xnT[c+2][j] = y2; sm->xnT[c+3][j] = y3;
        }
        __syncthreads();

        // ---- Phase 2: L = xn@w1+b1, R = xn@w2+b2 (fused k-loop; n = tid) ----
        {
            const int n = tid;
            float aL[NJ], aR[NJ];
            #pragma unroll
            for (int j = 0; j < NJ; ++j) { aL[j] = 0.f; aR[j] = 0.f; }
            #pragma unroll 4
            for (int k = 0; k < ND; ++k) {
                const float wa = w1[k*(2*ND) + n];
                const float wb = w2[k*(2*ND) + n];
                const float4* xr = reinterpret_cast<const float4*>(&sm->xnT[k][0]);
                const float4 a0 = xr[0], a1 = xr[1], a2 = xr[2], a3 = xr[3];
                const float x16 = sm->xnT[k][16];
                aL[0]  = fmaf(a0.x, wa, aL[0]);   aR[0]  = fmaf(a0.x, wb, aR[0]);
                aL[1]  = fmaf(a0.y, wa, aL[1]);   aR[1]  = fmaf(a0.y, wb, aR[1]);
                aL[2]  = fmaf(a0.z, wa, aL[2]);   aR[2]  = fmaf(a0.z, wb, aR[2]);
                aL[3]  = fmaf(a0.w, wa, aL[3]);   aR[3]  = fmaf(a0.w, wb, aR[3]);
                aL[4]  = fmaf(a1.x, wa, aL[4]);   aR[4]  = fmaf(a1.x, wb, aR[4]);
                aL[5]  = fmaf(a1.y, wa, aL[5]);   aR[5]  = fmaf(a1.y, wb, aR[5]);
                aL[6]  = fmaf(a1.z, wa, aL[6]);   aR[6]  = fmaf(a1.z, wb, aR[6]);
                aL[7]  = fmaf(a1.w, wa, aL[7]);   aR[7]  = fmaf(a1.w, wb, aR[7]);
                aL[8]  = fmaf(a2.x, wa, aL[8]);   aR[8]  = fmaf(a2.x, wb, aR[8]);
                aL[9]  = fmaf(a2.y, wa, aL[9]);   aR[9]  = fmaf(a2.y, wb, aR[9]);
                aL[10] = fmaf(a2.z, wa, aL[10]);  aR[10] = fmaf(a2.z, wb, aR[10]);
                aL[11] = fmaf(a2.w, wa, aL[11]);  aR[11] = fmaf(a2.w, wb, aR[11]);
                aL[12] = fmaf(a3.x, wa, aL[12]);  aR[12] = fmaf(a3.x, wb, aR[12]);
                aL[13] = fmaf(a3.y, wa, aL[13]);  aR[13] = fmaf(a3.y, wb, aR[13]);
                aL[14] = fmaf(a3.z, wa, aL[14]);  aR[14] = fmaf(a3.z, wb, aR[14]);
                aL[15] = fmaf(a3.w, wa, aL[15]);  aR[15] = fmaf(a3.w, wb, aR[15]);
                aL[16] = fmaf(x16,  wa, aL[16]);  aR[16] = fmaf(x16,  wb, aR[16]);
            }
            const float bb1 = sm->b1s[n], bb2 = sm->b2s[n];
            #pragma unroll
            for (int j = 0; j < NJ; ++j) {
                sm->Ls[j][n] = aL[j] + bb1;
                sm->Rs[j][n] = aR[j] + bb2;
            }
        }
        __syncthreads();

        // ---- Phase 3: V = xn@v_w + v_b (threads split by j-halves; n = tid&127) ----
        {
            const int n = tid & 127;
            float aV[9];
            #pragma unroll
            for (int t = 0; t < 9; ++t) aV[t] = 0.f;
            if (tid < 128) {
                // rows 0..7 and 16
                #pragma unroll 4
                for (int k = 0; k < ND; ++k) {
                    const float wv = vw[k*ND + n];
                    const float4* xr = reinterpret_cast<const float4*>(&sm->xnT[k][0]);
                    const float4 a0 = xr[0], a1 = xr[1];
                    const float x16 = sm->xnT[k][16];
                    aV[0] = fmaf(a0.x, wv, aV[0]);
                    aV[1] = fmaf(a0.y, wv, aV[1]);
                    aV[2] = fmaf(a0.z, wv, aV[2]);
                    aV[3] = fmaf(a0.w, wv, aV[3]);
                    aV[4] = fmaf(a1.x, wv, aV[4]);
                    aV[5] = fmaf(a1.y, wv, aV[5]);
                    aV[6] = fmaf(a1.z, wv, aV[6]);
                    aV[7] = fmaf(a1.w, wv, aV[7]);
                    aV[8] = fmaf(x16,  wv, aV[8]);
                }
                const float bb = sm->vbs[n];
                #pragma unroll
                for (int t = 0; t < 8; ++t) sm->Vs[t][n] = aV[t] + bb;
                sm->Vs[16][n] = aV[8] + bb;
            } else {
                // rows 8..15
                #pragma unroll 4
                for (int k = 0; k < ND; ++k) {
                    const float wv = vw[k*ND + n];
                    const float4* xr = reinterpret_cast<const float4*>(&sm->xnT[k][8]);
                    const float4 a2 = xr[0], a3 = xr[1];
                    aV[0] = fmaf(a2.x, wv, aV[0]);
                    aV[1] = fmaf(a2.y, wv, aV[1]);
                    aV[2] = fmaf(a2.z, wv, aV[2]);
                    aV[3] = fmaf(a2.w, wv, aV[3]);
                    aV[4] = fmaf(a3.x, wv, aV[4]);
                    aV[5] = fmaf(a3.y, wv, aV[5]);
                    aV[6] = fmaf(a3.z, wv, aV[6]);
                    aV[7] = fmaf(a3.w, wv, aV[7]);
                }
                const float bb = sm->vbs[n];
                #pragma unroll
                for (int t = 0; t < 8; ++t) sm->Vs[8+t][n] = aV[t] + bb;
            }
        }
        __syncthreads();

        // ---- Phase 4: attention scores on the 49 adjacency pairs × 2 heads ----
        for (int t = wid; t < 98; t += 8) {
            const int h  = (t >= 49);
            const int e  = t - 49*h;
            const int ii = c_edge_i[e];
            const int jn = c_nbr[e];
            const float4 lv = reinterpret_cast<const float4*>(&sm->Ls[ii][h*ND])[lane];
            const float4 rv = reinterpret_cast<const float4*>(&sm->Rs[jn][h*ND])[lane];
            const float4 pw = reinterpret_cast<const float4*>(sm->psW)[lane];
            float z, acc;
            z = lv.x + rv.x; z = fmaxf(z, 0.2f*z); acc  = z*pw.x;
            z = lv.y + rv.y; z = fmaxf(z, 0.2f*z); acc += z*pw.y;
            z = lv.z + rv.z; z = fmaxf(z, 0.2f*z); acc += z*pw.z;
            z = lv.w + rv.w; z = fmaxf(z, 0.2f*z); acc += z*pw.w;
            acc = wredsum(acc);
            if (lane == 0) sm->scs[t] = acc + sm->ps_b0;
        }
        __syncthreads();

        // ---- Phase 5: softmax (<=5 nbrs) + aggregate + gelu + skip combine -> xs ----
        for (int t = wid; t < 2*NJ; t += 8) {
            const int h  = t / NJ;
            const int i  = t - h*NJ;
            const int o0 = c_nbr_off[i];
            const int deg = c_nbr_off[i+1] - o0;
            float sc[5]; int nb[5];
            #pragma unroll
            for (int d = 0; d < 5; ++d) {
                const bool valid = d < deg;
                sc[d] = valid ? sm->scs[h*49 + o0 + d] : -1e30f;
                nb[d] = valid ? c_nbr[o0 + d] : 0;
            }
            float m = sc[0];
            #pragma unroll
            for (int d = 1; d < 5; ++d) m = fmaxf(m, sc[d]);
            float den = 0.f;
            #pragma unroll
            for (int d = 0; d < 5; ++d) { sc[d] = expf(sc[d] - m); den += sc[d]; }
            const float inv = 1.0f / den;
            float acc0 = 0.f, acc1 = 0.f;
            #pragma unroll
            for (int d = 0; d < 5; ++d) {
                const float* vr = &sm->Vs[nb[d]][h*NDH];
                acc0 = fmaf(sc[d], vr[lane],      acc0);
                acc1 = fmaf(sc[d], vr[lane + 32], acc1);
            }
            acc0 *= inv; acc1 *= inv;
            acc0 = 0.5f*acc0*(1.0f + erff(acc0*0.70710678118654752f));
            acc1 = 0.5f*acc1*(1.0f + erff(acc1*0.70710678118654752f));
            const float sk = sm->skipv[i];
            const int c0 = h*NDH + lane;
            sm->xs[i][c0]      = (1.0f - sk)*acc0 + sk*sm->x0s[i][c0];
            sm->xs[i][c0+32]   = (1.0f - sk)*acc1 + sk*sm->x0s[i][c0+32];
        }
        __syncthreads();
    }

    // ---- write result ----
    float* og_out = out + (size_t)tile * NJ * ND;
    for (int j = wid; j < NJ; j += 8) {
        reinterpret_cast<float4*>(og_out + j*ND)[lane] =
            reinterpret_cast<const float4*>(sm->xs[j])[lane];
    }
}

extern "C" void kernel_launch(void* const* d_in, const int* in_sizes, int n_in,
                              void* d_out, int out_size) {
    const float* x   = (const float*)d_in[0];
    const float* og  = (const float*)d_in[1];
    const float* ob  = (const float*)d_in[2];
    const float* lg  = (const float*)d_in[3];
    const float* lb  = (const float*)d_in[4];
    const float* aw  = (const float*)d_in[5];
    const float* ab  = (const float*)d_in[6];
    const float* w1  = (const float*)d_in[7];
    const float* b1  = (const float*)d_in[8];
    const float* w2  = (const float*)d_in[9];
    const float* b2  = (const float*)d_in[10];
    const float* psw = (const float*)d_in[11];
    const float* psb = (const float*)d_in[12];
    const float* vw  = (const float*)d_in[13];
    const float* vb  = (const float*)d_in[14];

    const int tiles = in_sizes[0] / (NJ * ND);  // 3888
    const size_t smem_bytes = sizeof(SmemLayout);
    cudaFuncSetAttribute(spatial_appnp_kernel,
                         cudaFuncAttributeMaxDynamicSharedMemorySize,
                         (int)smem_bytes);
    spatial_appnp_kernel<<<tiles, NTHREADS, smem_bytes>>>(
        x, og, ob, lg, lb, aw, ab, w1, b1, w2, b2, psw, psb, vw, vb,
        (float*)d_out);
}

// round 4
// speedup vs baseline: 2.0520x; 2.0520x over previous
#include <cuda_runtime.h>
#include <math.h>

#define NJ 17
#define ND 128
#define NH 2
#define NDH 64
#define NITER 4
#define LNEPS 1e-5f
#define NTHREADS 256
#define XSTR 20          // padded row stride for transposed xn tile

typedef unsigned long long ull;

// ---- fixed 17-node skeleton adjacency (incl. self), flattened neighbor lists ----
__constant__ int c_nbr_off[18] = {0,4,7,10,12,15,18,20,23,28,31,33,36,39,41,44,47,49};
__constant__ int c_nbr[49] = {
    0,1,4,7,  0,1,2,  1,2,3,  2,3,  0,4,5,  4,5,6,  5,6,  0,7,8,
    7,8,9,11,14,  8,9,10,  9,10,  8,11,12,  11,12,13,  12,13,
    8,14,15,  14,15,16,  15,16};
__constant__ int c_edge_i[49] = {
    0,0,0,0,  1,1,1,  2,2,2,  3,3,  4,4,4,  5,5,5,  6,6,  7,7,7,
    8,8,8,8,8,  9,9,9,  10,10,  11,11,11,  12,12,12,  13,13,
    14,14,14,  15,15,15,  16,16};

// float4/LDS.128 members must be 16B aligned (R1 lesson).
struct SmemLayout {
    alignas(16) float xs[NJ][ND];
    alignas(16) float x0s[NJ][ND];
    alignas(16) float xnT[ND][XSTR];   // row stride 80B (16-mult)
    alignas(16) float Ls[NJ][2*ND];
    alignas(16) float Rs[NJ][2*ND];
    alignas(16) float Vs[NJ][ND];
    alignas(16) float scs[2*49];
    alignas(16) float skipv[NJ];
    alignas(16) float lnG[ND];
    alignas(16) float lnB[ND];
    alignas(16) float aW[ND];
    alignas(16) float psW[ND];
    alignas(16) float vbs[ND];
    alignas(16) float b1s[2*ND];
    alignas(16) float b2s[2*ND];
    alignas(16) float alpha_b0;
    float ps_b0;
};

__device__ __forceinline__ float wredsum(float v) {
    #pragma unroll
    for (int o = 16; o; o >>= 1) v += __shfl_xor_sync(0xffffffffu, v, o);
    return v;
}

// ---- packed fp32x2 helpers (sm_103a FFMA2 path) ----
__device__ __forceinline__ void ffma2(ull& d, ull a, ull b) {
    asm("fma.rn.f32x2 %0, %1, %2, %0;" : "+l"(d) : "l"(a), "l"(b));
}
__device__ __forceinline__ ull pack2(float lo, float hi) {
    ull r; asm("mov.b64 %0, {%1, %2};" : "=l"(r) : "f"(lo), "f"(hi)); return r;
}
__device__ __forceinline__ float2 unpack2(ull v) {
    float lo, hi; asm("mov.b64 {%0, %1}, %2;" : "=f"(lo), "=f"(hi) : "l"(v));
    return make_float2(lo, hi);
}

__global__ void __launch_bounds__(NTHREADS, 2)
spatial_appnp_kernel(
    const float* __restrict__ x,
    const float* __restrict__ og,  const float* __restrict__ ob,
    const float* __restrict__ lg,  const float* __restrict__ lb,
    const float* __restrict__ aw,  const float* __restrict__ ab,
    const float* __restrict__ w1,  const float* __restrict__ b1,
    const float* __restrict__ w2,  const float* __restrict__ b2,
    const float* __restrict__ psw, const float* __restrict__ psb,
    const float* __restrict__ vw,  const float* __restrict__ vb,
    float* __restrict__ out)
{
    extern __shared__ float smem_raw[];
    SmemLayout* sm = reinterpret_cast<SmemLayout*>(smem_raw);

    const int tid  = threadIdx.x;
    const int lane = tid & 31;
    const int wid  = tid >> 5;
    const int tile = blockIdx.x;
    const float* xg = x + (size_t)tile * NJ * ND;

    for (int i = tid; i < ND; i += NTHREADS) {
        sm->lnG[i] = lg[i]; sm->lnB[i] = lb[i];
        sm->aW[i]  = aw[i]; sm->psW[i] = psw[i];
        sm->vbs[i] = vb[i];
    }
    for (int i = tid; i < 2*ND; i += NTHREADS) { sm->b1s[i] = b1[i]; sm->b2s[i] = b2[i]; }
    if (tid == 0) { sm->alpha_b0 = ab[0]; sm->ps_b0 = psb[0]; }

    // ---- outer LayerNorm: x -> xs, x0s ----
    for (int j = wid; j < NJ; j += 8) {
        const float4 v = reinterpret_cast<const float4*>(xg + j*ND)[lane];
        const float mean = wredsum(v.x+v.y+v.z+v.w) * (1.0f/ND);
        const float d0=v.x-mean, d1=v.y-mean, d2=v.z-mean, d3=v.w-mean;
        const float var = wredsum(d0*d0+d1*d1+d2*d2+d3*d3) * (1.0f/ND);
        const float rs = rsqrtf(var + LNEPS);
        const int c = lane*4;
        float4 r;
        r.x = d0*rs*og[c+0] + ob[c+0];
        r.y = d1*rs*og[c+1] + ob[c+1];
        r.z = d2*rs*og[c+2] + ob[c+2];
        r.w = d3*rs*og[c+3] + ob[c+3];
        reinterpret_cast<float4*>(sm->xs[j])[lane]  = r;
        reinterpret_cast<float4*>(sm->x0s[j])[lane] = r;
    }
    __syncthreads();

    for (int it = 0; it < NITER; ++it) {
        // ---- Phase 1: inner LN(xs) -> xnT (transposed), skip gate ----
        for (int j = wid; j < NJ; j += 8) {
            const float4 v = reinterpret_cast<const float4*>(sm->xs[j])[lane];
            const float mean = wredsum(v.x+v.y+v.z+v.w) * (1.0f/ND);
            const float d0=v.x-mean, d1=v.y-mean, d2=v.z-mean, d3=v.w-mean;
            const float var = wredsum(d0*d0+d1*d1+d2*d2+d3*d3) * (1.0f/ND);
            const float rs = rsqrtf(var + LNEPS);
            const int c = lane*4;
            const float y0 = d0*rs*sm->lnG[c+0] + sm->lnB[c+0];
            const float y1 = d1*rs*sm->lnG[c+1] + sm->lnB[c+1];
            const float y2 = d2*rs*sm->lnG[c+2] + sm->lnB[c+2];
            const float y3 = d3*rs*sm->lnG[c+3] + sm->lnB[c+3];
            float dot = y0*sm->aW[c+0] + y1*sm->aW[c+1] + y2*sm->aW[c+2] + y3*sm->aW[c+3];
            dot = wredsum(dot);
            if (lane == 0)
                sm->skipv[j] = 1.0f / (1.0f + expf(-(dot + sm->alpha_b0)));
            sm->xnT[c+0][j] = y0; sm->xnT[c+1][j] = y1;
            sm->xnT[c+2][j] = y2; sm->xnT[c+3][j] = y3;
        }
        __syncthreads();

        // ---- Phase 2+3 fused: L = xn@w1+b1, R = xn@w2+b2, V = xn@v_w+v_b ----
        // Thread tid owns column n=tid of L and R (n in [0,256)) and column
        // (tid&127) of V for half the rows. Packed FFMA2 pairs rows (2q,2q+1).
        {
            const int n  = tid;
            const int nv = tid & 127;
            ull accL[8], accR[8], accV[4];
            float aL16 = 0.f, aR16 = 0.f, aV16 = 0.f;
            #pragma unroll
            for (int q = 0; q < 8; ++q) { accL[q] = 0ull; accR[q] = 0ull; }
            #pragma unroll
            for (int q = 0; q < 4; ++q) accV[q] = 0ull;

            const float* w1p = w1 + n;
            const float* w2p = w2 + n;
            const float* vwp = vw + nv;

            if (tid < 128) {
                // V rows 0..7 and 16
                #pragma unroll 4
                for (int k = 0; k < ND; ++k) {
                    const float wa = w1p[k*(2*ND)];
                    const float wb = w2p[k*(2*ND)];
                    const float wv = vwp[k*ND];
                    const ull waa = pack2(wa, wa);
                    const ull wbb = pack2(wb, wb);
                    const ull wvv = pack2(wv, wv);
                    const ulonglong2* xr = reinterpret_cast<const ulonglong2*>(&sm->xnT[k][0]);
                    const ulonglong2 pA = xr[0];   // (x0,x1),(x2,x3)
                    const ulonglong2 pB = xr[1];   // (x4,x5),(x6,x7)
                    const ulonglong2 pC = xr[2];   // (x8,x9),(x10,x11)
                    const ulonglong2 pD = xr[3];   // (x12,x13),(x14,x15)
                    const float x16 = sm->xnT[k][16];
                    ffma2(accL[0], pA.x, waa); ffma2(accR[0], pA.x, wbb);
                    ffma2(accL[1], pA.y, waa); ffma2(accR[1], pA.y, wbb);
                    ffma2(accL[2], pB.x, waa); ffma2(accR[2], pB.x, wbb);
                    ffma2(accL[3], pB.y, waa); ffma2(accR[3], pB.y, wbb);
                    ffma2(accL[4], pC.x, waa); ffma2(accR[4], pC.x, wbb);
                    ffma2(accL[5], pC.y, waa); ffma2(accR[5], pC.y, wbb);
                    ffma2(accL[6], pD.x, waa); ffma2(accR[6], pD.x, wbb);
                    ffma2(accL[7], pD.y, waa); ffma2(accR[7], pD.y, wbb);
                    aL16 = fmaf(x16, wa, aL16);
                    aR16 = fmaf(x16, wb, aR16);
                    ffma2(accV[0], pA.x, wvv); ffma2(accV[1], pA.y, wvv);
                    ffma2(accV[2], pB.x, wvv); ffma2(accV[3], pB.y, wvv);
                    aV16 = fmaf(x16, wv, aV16);
                }
            } else {
                // V rows 8..15
                #pragma unroll 4
                for (int k = 0; k < ND; ++k) {
                    const float wa = w1p[k*(2*ND)];
                    const float wb = w2p[k*(2*ND)];
                    const float wv = vwp[k*ND];
                    const ull waa = pack2(wa, wa);
                    const ull wbb = pack2(wb, wb);
                    const ull wvv = pack2(wv, wv);
                    const ulonglong2* xr = reinterpret_cast<const ulonglong2*>(&sm->xnT[k][0]);
                    const ulonglong2 pA = xr[0];
                    const ulonglong2 pB = xr[1];
                    const ulonglong2 pC = xr[2];
                    const ulonglong2 pD = xr[3];
                    const float x16 = sm->xnT[k][16];
                    ffma2(accL[0], pA.x, waa); ffma2(accR[0], pA.x, wbb);
                    ffma2(accL[1], pA.y, waa); ffma2(accR[1], pA.y, wbb);
                    ffma2(accL[2], pB.x, waa); ffma2(accR[2], pB.x, wbb);
                    ffma2(accL[3], pB.y, waa); ffma2(accR[3], pB.y, wbb);
                    ffma2(accL[4], pC.x, waa); ffma2(accR[4], pC.x, wbb);
                    ffma2(accL[5], pC.y, waa); ffma2(accR[5], pC.y, wbb);
                    ffma2(accL[6], pD.x, waa); ffma2(accR[6], pD.x, wbb);
                    ffma2(accL[7], pD.y, waa); ffma2(accR[7], pD.y, wbb);
                    aL16 = fmaf(x16, wa, aL16);
                    aR16 = fmaf(x16, wb, aR16);
                    ffma2(accV[0], pC.x, wvv); ffma2(accV[1], pC.y, wvv);
                    ffma2(accV[2], pD.x, wvv); ffma2(accV[3], pD.y, wvv);
                }
            }

            const float bb1 = sm->b1s[n], bb2 = sm->b2s[n];
            #pragma unroll
            for (int q = 0; q < 8; ++q) {
                const float2 l2 = unpack2(accL[q]);
                const float2 r2 = unpack2(accR[q]);
                sm->Ls[2*q  ][n] = l2.x + bb1;
                sm->Ls[2*q+1][n] = l2.y + bb1;
                sm->Rs[2*q  ][n] = r2.x + bb2;
                sm->Rs[2*q+1][n] = r2.y + bb2;
            }
            sm->Ls[16][n] = aL16 + bb1;
            sm->Rs[16][n] = aR16 + bb2;

            const float bbv = sm->vbs[nv];
            if (tid < 128) {
                #pragma unroll
                for (int q = 0; q < 4; ++q) {
                    const float2 v2 = unpack2(accV[q]);
                    sm->Vs[2*q  ][nv] = v2.x + bbv;
                    sm->Vs[2*q+1][nv] = v2.y + bbv;
                }
                sm->Vs[16][nv] = aV16 + bbv;
            } else {
                #pragma unroll
                for (int q = 0; q < 4; ++q) {
                    const float2 v2 = unpack2(accV[q]);
                    sm->Vs[8+2*q  ][nv] = v2.x + bbv;
                    sm->Vs[8+2*q+1][nv] = v2.y + bbv;
                }
            }
        }
        __syncthreads();

        // ---- Phase 4: attention scores on the 49 adjacency pairs × 2 heads ----
        for (int t = wid; t < 98; t += 8) {
            const int h  = (t >= 49);
            const int e  = t - 49*h;
            const int ii = c_edge_i[e];
            const int jn = c_nbr[e];
            const float4 lv = reinterpret_cast<const float4*>(&sm->Ls[ii][h*ND])[lane];
            const float4 rv = reinterpret_cast<const float4*>(&sm->Rs[jn][h*ND])[lane];
            const float4 pw = reinterpret_cast<const float4*>(sm->psW)[lane];
            float z, acc;
            z = lv.x + rv.x; z = fmaxf(z, 0.2f*z); acc  = z*pw.x;
            z = lv.y + rv.y; z = fmaxf(z, 0.2f*z); acc += z*pw.y;
            z = lv.z + rv.z; z = fmaxf(z, 0.2f*z); acc += z*pw.z;
            z = lv.w + rv.w; z = fmaxf(z, 0.2f*z); acc += z*pw.w;
            acc = wredsum(acc);
            if (lane == 0) sm->scs[t] = acc + sm->ps_b0;
        }
        __syncthreads();

        // ---- Phase 5: softmax (<=5 nbrs) + aggregate + gelu + skip combine -> xs ----
        for (int t = wid; t < 2*NJ; t += 8) {
            const int h  = t / NJ;
            const int i  = t - h*NJ;
            const int o0 = c_nbr_off[i];
            const int deg = c_nbr_off[i+1] - o0;
            float sc[5]; int nb[5];
            #pragma unroll
            for (int d = 0; d < 5; ++d) {
                const bool valid = d < deg;
                sc[d] = valid ? sm->scs[h*49 + o0 + d] : -1e30f;
                nb[d] = valid ? c_nbr[o0 + d] : 0;
            }
            float m = sc[0];
            #pragma unroll
            for (int d = 1; d < 5; ++d) m = fmaxf(m, sc[d]);
            float den = 0.f;
            #pragma unroll
            for (int d = 0; d < 5; ++d) { sc[d] = expf(sc[d] - m); den += sc[d]; }
            const float inv = 1.0f / den;
            float acc0 = 0.f, acc1 = 0.f;
            #pragma unroll
            for (int d = 0; d < 5; ++d) {
                const float* vr = &sm->Vs[nb[d]][h*NDH];
                acc0 = fmaf(sc[d], vr[lane],      acc0);
                acc1 = fmaf(sc[d], vr[lane + 32], acc1);
            }
            acc0 *= inv; acc1 *= inv;
            acc0 = 0.5f*acc0*(1.0f + erff(acc0*0.70710678118654752f));
            acc1 = 0.5f*acc1*(1.0f + erff(acc1*0.70710678118654752f));
            const float sk = sm->skipv[i];
            const int c0 = h*NDH + lane;
            sm->xs[i][c0]      = (1.0f - sk)*acc0 + sk*sm->x0s[i][c0];
            sm->xs[i][c0+32]   = (1.0f - sk)*acc1 + sk*sm->x0s[i][c0+32];
        }
        __syncthreads();
    }

    // ---- write result ----
    float* og_out = out + (size_t)tile * NJ * ND;
    for (int j = wid; j < NJ; j += 8) {
        reinterpret_cast<float4*>(og_out + j*ND)[lane] =
            reinterpret_cast<const float4*>(sm->xs[j])[lane];
    }
}

extern "C" void kernel_launch(void* const* d_in, const int* in_sizes, int n_in,
                              void* d_out, int out_size) {
    const float* x   = (const float*)d_in[0];
    const float* og  = (const float*)d_in[1];
    const float* ob  = (const float*)d_in[2];
    const float* lg  = (const float*)d_in[3];
    const float* lb  = (const float*)d_in[4];
    const float* aw  = (const float*)d_in[5];
    const float* ab  = (const float*)d_in[6];
    const float* w1  = (const float*)d_in[7];
    const float* b1  = (const float*)d_in[8];
    const float* w2  = (const float*)d_in[9];
    const float* b2  = (const float*)d_in[10];
    const float* psw = (const float*)d_in[11];
    const float* psb = (const float*)d_in[12];
    const float* vw  = (const float*)d_in[13];
    const float* vb  = (const float*)d_in[14];

    const int tiles = in_sizes[0] / (NJ * ND);  // 3888
    const size_t smem_bytes = sizeof(SmemLayout);
    cudaFuncSetAttribute(spatial_appnp_kernel,
                         cudaFuncAttributeMaxDynamicSharedMemorySize,
                         (int)smem_bytes);
    spatial_appnp_kernel<<<tiles, NTHREADS, smem_bytes>>>(
        x, og, ob, lg, lb, aw, ab, w1, b1, w2, b2, psw, psb, vw, vb,
        (float*)d_out);
}